// round 7
// baseline (speedup 1.0000x reference)
#include <cuda_runtime.h>
#include <cuda_bf16.h>
#include <math.h>
#include <stdint.h>

// Problem dims (fixed per reference)
constexpr int S = 512;
constexpr int B = 256;
constexpr int I = 512;
constexpr int H = 512;
constexpr int M1 = S * B;
constexpr int BH = B * H;

// Panel layout: per row, per 16-k block kb, four 16B t-groups:
//   [0:4) hi pair(2t,2t+1)  [4:8) hi pair(2t+8,2t+9)
//   [8:12) lo pair(2t)      [12:16) lo pair(2t+8)
// Row stride 2112 B (132*16B, 132%8==4 -> conflict-free LDS.128).
constexpr int RSTR = 2112;
constexpr int SM_W = 0;                     // W panel: 64 rows * 2112 = 135168
constexpr int SM_A = 64 * RSTR;             // A panel: 16 rows * 2112 = 33792
constexpr int SMEM_P2 = 64 * RSTR + 16 * RSTR;   // 168960

// ===========================================================================
// Static device scratch (allocation-free)
// g_hfmt: h in fragment-ready format; per bm group: 16 rows x 128 uint4.
// ===========================================================================
__device__ uint4 g_hfmt[2][16][16 * 128];
__device__ uint32_t g_whl[H * H];           // packed {bf16 hi<<16 | bf16 lo} of Ww

__device__ __forceinline__ uint32_t pack_hl(float x) {
    __nv_bfloat16 h = __float2bfloat16(x);
    float r = x - __bfloat162float(h);
    __nv_bfloat16 l = __float2bfloat16(r);
    return (((uint32_t)__bfloat16_as_ushort(h)) << 16) |
           (uint32_t)__bfloat16_as_ushort(l);
}

// split pair (a,b) into bf16 hi-word and lo-word (a in low half)
__device__ __forceinline__ void split_pair(float a, float b,
                                           uint32_t& hiw, uint32_t& low) {
    __nv_bfloat16 ah = __float2bfloat16(a), bh = __float2bfloat16(b);
    float ar = a - __bfloat162float(ah);
    float br = b - __bfloat162float(bh);
    __nv_bfloat16 al = __float2bfloat16(ar), bl = __float2bfloat16(br);
    hiw = (((uint32_t)__bfloat16_as_ushort(bh)) << 16) | __bfloat16_as_ushort(ah);
    low = (((uint32_t)__bfloat16_as_ushort(bl)) << 16) | __bfloat16_as_ushort(al);
}

__global__ void __launch_bounds__(256) convert_W(const float* __restrict__ Ww) {
    int i = blockIdx.x * blockDim.x + threadIdx.x;
    if (i < H * H) g_whl[i] = pack_hl(Ww[i]);
}

// ===========================================================================
// Cluster barrier (HW path; ~0.25us vs ~1.5-3us of L2 polling)
// ===========================================================================
__device__ __forceinline__ void cluster_arrive() {
    asm volatile("barrier.cluster.arrive.aligned;" ::: "memory");
}
__device__ __forceinline__ void cluster_wait() {
    asm volatile("barrier.cluster.wait.aligned;" ::: "memory");
}

// ===========================================================================
// mma.sync m16n8k16 bf16 (portable tensor-core path on sm_103)
// ===========================================================================
__device__ __forceinline__ void mma_bf16(float c[4],
                                         uint32_t a0, uint32_t a1,
                                         uint32_t a2, uint32_t a3,
                                         uint32_t b0, uint32_t b1) {
    asm volatile(
        "mma.sync.aligned.m16n8k16.row.col.f32.bf16.bf16.f32 "
        "{%0,%1,%2,%3}, {%4,%5,%6,%7}, {%8,%9}, {%0,%1,%2,%3};"
        : "+f"(c[0]), "+f"(c[1]), "+f"(c[2]), "+f"(c[3])
        : "r"(a0), "r"(a1), "r"(a2), "r"(a3), "r"(b0), "r"(b1));
}

// ===========================================================================
// Phase 1: xV = x @ Vw^T + Vb  (fp32 SIMT, known-good)
// ===========================================================================
__global__ void __launch_bounds__(256) phase1_gemm(
    const float* __restrict__ A,
    const float* __restrict__ W,
    const float* __restrict__ bias,
    float* __restrict__ C)
{
    constexpr int BM = 128, BN = 128, BK = 16;
    constexpr int K = I;
    constexpr int PAD = 4;
    __shared__ float As[BK][BM + PAD];
    __shared__ float Bs[BK][BN + PAD];

    const int tid = threadIdx.x;
    const int bn = blockIdx.x;
    const int bm = blockIdx.y;

    const float* Ap = A + (size_t)bm * BM * K;
    const float* Wp = W + (size_t)bn * BN * K;

    const int ty = tid / 16;
    const int tx = tid % 16;

    float acc[8][8];
    #pragma unroll
    for (int i = 0; i < 8; i++)
        #pragma unroll
        for (int j = 0; j < 8; j++) acc[i][j] = 0.0f;

    for (int k0 = 0; k0 < K; k0 += BK) {
        #pragma unroll
        for (int l = 0; l < 2; l++) {
            int f   = tid + l * 256;
            int row = f >> 2;
            int c4  = (f & 3) * 4;
            float4 av = *reinterpret_cast<const float4*>(Ap + (size_t)row * K + k0 + c4);
            As[c4 + 0][row] = av.x; As[c4 + 1][row] = av.y;
            As[c4 + 2][row] = av.z; As[c4 + 3][row] = av.w;
            float4 bv = *reinterpret_cast<const float4*>(Wp + (size_t)row * K + k0 + c4);
            Bs[c4 + 0][row] = bv.x; Bs[c4 + 1][row] = bv.y;
            Bs[c4 + 2][row] = bv.z; Bs[c4 + 3][row] = bv.w;
        }
        __syncthreads();
        #pragma unroll
        for (int k = 0; k < BK; k++) {
            float ar[8], br[8];
            *reinterpret_cast<float4*>(ar)     = *reinterpret_cast<const float4*>(&As[k][ty * 8]);
            *reinterpret_cast<float4*>(ar + 4) = *reinterpret_cast<const float4*>(&As[k][ty * 8 + 4]);
            *reinterpret_cast<float4*>(br)     = *reinterpret_cast<const float4*>(&Bs[k][tx * 8]);
            *reinterpret_cast<float4*>(br + 4) = *reinterpret_cast<const float4*>(&Bs[k][tx * 8 + 4]);
            #pragma unroll
            for (int i = 0; i < 8; i++)
                #pragma unroll
                for (int j = 0; j < 8; j++)
                    acc[i][j] = fmaf(ar[i], br[j], acc[i][j]);
        }
        __syncthreads();
    }
    const int rowb = bm * BM + ty * 8;
    const int colb = bn * BN + tx * 8;
    float bvals[8];
    #pragma unroll
    for (int j = 0; j < 8; j++) bvals[j] = bias[colb + j];
    #pragma unroll
    for (int i = 0; i < 8; i++) {
        float* cp = C + (size_t)(rowb + i) * H + colb;
        float4 v0, v1;
        v0.x = acc[i][0] + bvals[0]; v0.y = acc[i][1] + bvals[1];
        v0.z = acc[i][2] + bvals[2]; v0.w = acc[i][3] + bvals[3];
        v1.x = acc[i][4] + bvals[4]; v1.y = acc[i][5] + bvals[5];
        v1.z = acc[i][6] + bvals[6]; v1.w = acc[i][7] + bvals[7];
        *reinterpret_cast<float4*>(cp)     = v0;
        *reinterpret_cast<float4*>(cp + 4) = v1;
    }
}

// ===========================================================================
// Phase 2: persistent mma.sync bf16x3 recurrence with 8-CTA clusters.
// Grid: (bn=8, bm=16) = 128 CTAs, cluster (8,1,1) = one bm row group.
// CTA tile: 16(M) x 64(N). 128 threads, 4 warps; warp ni owns n16 slice.
// ===========================================================================
__global__ void __launch_bounds__(128, 1) __cluster_dims__(8, 1, 1)
rnn_steps_mma(const float* __restrict__ Wb, float* __restrict__ io)
{
    extern __shared__ char smem[];

    const int tid  = threadIdx.x;
    const int wid  = tid >> 5;
    const int lane = tid & 31;
    const int bn   = blockIdx.x;               // 0..7
    const int bm   = blockIdx.y;               // 0..15
    const int Rg0  = bm * 16;                  // first global row of tile
    const int cg0  = bn * 64;                  // first global col of tile

    const int ni = wid;                        // 0..3
    const int n0 = ni * 16;
    const int g  = lane >> 2;                  // 0..7
    const int t  = lane & 3;                   // 0..3

    // ---- Format resident W panel once (rows = out cols cg0..cg0+63) ----
    for (int l = 0; l < 64; l++) {
        int j  = tid + (l << 7);               // 0..8191
        int r  = j >> 7;                       // 0..63
        int k4 = (j & 127) * 4;                // 0..508
        uint4 v = *reinterpret_cast<const uint4*>(
            &g_whl[(size_t)(cg0 + r) * 512 + k4]);
        uint32_t hi0 = __byte_perm(v.x, v.y, 0x7632);
        uint32_t lo0 = __byte_perm(v.x, v.y, 0x5410);
        uint32_t hi1 = __byte_perm(v.z, v.w, 0x7632);
        uint32_t lo1 = __byte_perm(v.z, v.w, 0x5410);
        int kb   = k4 >> 4;
        int rem  = k4 & 15;
        int slot = (rem >= 8) ? 4 : 0;
        int t0   = (rem & 7) >> 1;
        char* base = smem + SM_W + r * RSTR + kb * 64 + t0 * 16 + slot;
        *reinterpret_cast<uint32_t*>(base)      = hi0;
        *reinterpret_cast<uint32_t*>(base + 8)  = lo0;
        *reinterpret_cast<uint32_t*>(base + 16) = hi1;
        *reinterpret_cast<uint32_t*>(base + 24) = lo1;
    }

    // fragment pointers (constant across steps)
    const char* aB = smem + SM_A + g * RSTR + t * 16;                 // rows g, g+8
    const char* bB = smem + SM_W + (n0 + g) * RSTR + t * 16;          // + 8*RSTR

    // per-lane output coords
    const int orow0 = Rg0 + g;                 // and +8
    const int c0    = cg0 + n0 + 2 * t;        // cols c0,c0+1 and c0+8,c0+9
    const float2 wbA = *reinterpret_cast<const float2*>(Wb + c0);
    const float2 wbB = *reinterpret_cast<const float2*>(Wb + c0 + 8);
    // byte offset of this lane's granule within a g_hfmt row (2048 B rows)
    const int goff = ((cg0 + n0) >> 4) * 64 + t * 16;

    __syncthreads();   // W panel ready

    // ---- t = 0 : h_0 = tanh(xV_0 + Wb) ----
    {
        const int r  = tid >> 3;               // 0..15 local row
        const int c8 = (tid & 7) * 8;          // 0,8,..,56 local col
        const int gr = Rg0 + r;
        const float* xvp = io + (size_t)gr * H + cg0 + c8;
        float4 xv0 = __ldcg(reinterpret_cast<const float4*>(xvp));
        float4 xv1 = __ldcg(reinterpret_cast<const float4*>(xvp + 4));
        const float4 wb0 = *reinterpret_cast<const float4*>(Wb + cg0 + c8);
        const float4 wb1 = *reinterpret_cast<const float4*>(Wb + cg0 + c8 + 4);
        float h[8];
        h[0] = tanhf(xv0.x + wb0.x); h[1] = tanhf(xv0.y + wb0.y);
        h[2] = tanhf(xv0.z + wb0.z); h[3] = tanhf(xv0.w + wb0.w);
        h[4] = tanhf(xv1.x + wb1.x); h[5] = tanhf(xv1.y + wb1.y);
        h[6] = tanhf(xv1.z + wb1.z); h[7] = tanhf(xv1.w + wb1.w);
        float* op = io + (size_t)gr * H + cg0 + c8;
        *reinterpret_cast<float4*>(op)     = make_float4(h[0], h[1], h[2], h[3]);
        *reinterpret_cast<float4*>(op + 4) = make_float4(h[4], h[5], h[6], h[7]);
        char* gbase = reinterpret_cast<char*>(&g_hfmt[0][bm][0]) + r * 2048;
        #pragma unroll
        for (int p = 0; p < 4; p++) {
            int gcol = cg0 + c8 + 2 * p;
            int km   = gcol & 15;
            int tg   = (km & 7) >> 1;
            int sl   = (km >= 8) ? 4 : 0;
            int kb   = gcol >> 4;
            uint32_t hiw, low;
            split_pair(h[2 * p], h[2 * p + 1], hiw, low);
            char* ptr = gbase + kb * 64 + tg * 16 + sl;
            __stcg(reinterpret_cast<uint32_t*>(ptr), hiw);
            __stcg(reinterpret_cast<uint32_t*>(ptr + 8), low);
        }
    }
    cluster_arrive();
    cluster_wait();

    // ---- steps 1 .. S-1 ----
    for (int ts = 1; ts < S; ++ts) {
        // xV prefetch (independent of h_{t-1})
        const float* iot = io + (size_t)ts * BH;
        float2 xva0 = __ldcg(reinterpret_cast<const float2*>(iot + (size_t)orow0 * H + c0));
        float2 xva1 = __ldcg(reinterpret_cast<const float2*>(iot + (size_t)orow0 * H + c0 + 8));
        float2 xvb0 = __ldcg(reinterpret_cast<const float2*>(iot + (size_t)(orow0 + 8) * H + c0));
        float2 xvb1 = __ldcg(reinterpret_cast<const float2*>(iot + (size_t)(orow0 + 8) * H + c0 + 8));

        // stage h_{t-1} panel: 16 rows x 128 uint4 (already fragment-format)
        const uint4* src = &g_hfmt[(ts + 1) & 1][bm][0];
        {
            uint4 v[16];
            #pragma unroll
            for (int l = 0; l < 16; l++) {
                int j = tid + (l << 7);        // 0..2047
                v[l] = __ldcg(src + j);
            }
            #pragma unroll
            for (int l = 0; l < 16; l++) {
                int j = tid + (l << 7);
                int r = j >> 7;                // 0..15
                int c = j & 127;               // 0..127
                *reinterpret_cast<uint4*>(smem + SM_A + r * RSTR + c * 16) = v[l];
            }
        }
        __syncthreads();

        float chh0[4] = {0.f, 0.f, 0.f, 0.f};
        float chl0[4] = {0.f, 0.f, 0.f, 0.f};
        float clh0[4] = {0.f, 0.f, 0.f, 0.f};
        float chh1[4] = {0.f, 0.f, 0.f, 0.f};
        float chl1[4] = {0.f, 0.f, 0.f, 0.f};
        float clh1[4] = {0.f, 0.f, 0.f, 0.f};

        #pragma unroll 8
        for (int kb = 0; kb < 32; ++kb) {
            uint4 A1 = *reinterpret_cast<const uint4*>(aB + kb * 64);
            uint4 A2 = *reinterpret_cast<const uint4*>(aB + 8 * RSTR + kb * 64);
            uint4 B1 = *reinterpret_cast<const uint4*>(bB + kb * 64);
            uint4 B2 = *reinterpret_cast<const uint4*>(bB + 8 * RSTR + kb * 64);
            mma_bf16(chh0, A1.x, A2.x, A1.y, A2.y, B1.x, B1.y);   // hi*hi n-tile0
            mma_bf16(chh1, A1.x, A2.x, A1.y, A2.y, B2.x, B2.y);   // hi*hi n-tile1
            mma_bf16(chl0, A1.x, A2.x, A1.y, A2.y, B1.z, B1.w);   // hi*lo
            mma_bf16(chl1, A1.x, A2.x, A1.y, A2.y, B2.z, B2.w);
            mma_bf16(clh0, A1.z, A2.z, A1.w, A2.w, B1.x, B1.y);   // lo*hi
            mma_bf16(clh1, A1.z, A2.z, A1.w, A2.w, B2.x, B2.y);
        }

        // epilogue: h = tanh(acc + xV + Wb)
        float h00 = tanhf(chh0[0] + chl0[0] + clh0[0] + xva0.x + wbA.x);
        float h01 = tanhf(chh0[1] + chl0[1] + clh0[1] + xva0.y + wbA.y);
        float h08 = tanhf(chh1[0] + chl1[0] + clh1[0] + xva1.x + wbB.x);
        float h09 = tanhf(chh1[1] + chl1[1] + clh1[1] + xva1.y + wbB.y);
        float h20 = tanhf(chh0[2] + chl0[2] + clh0[2] + xvb0.x + wbA.x);
        float h21 = tanhf(chh0[3] + chl0[3] + clh0[3] + xvb0.y + wbA.y);
        float h28 = tanhf(chh1[2] + chl1[2] + clh1[2] + xvb1.x + wbB.x);
        float h29 = tanhf(chh1[3] + chl1[3] + clh1[3] + xvb1.y + wbB.y);

        // critical-path stores: fragment-format h for next step (one STG.128/row)
        {
            char* gb = reinterpret_cast<char*>(&g_hfmt[ts & 1][bm][0]);
            uint32_t hw0, lw0, hw1, lw1;
            split_pair(h00, h01, hw0, lw0);
            split_pair(h08, h09, hw1, lw1);
            __stcg(reinterpret_cast<uint4*>(gb + g * 2048 + goff),
                   make_uint4(hw0, hw1, lw0, lw1));
            split_pair(h20, h21, hw0, lw0);
            split_pair(h28, h29, hw1, lw1);
            __stcg(reinterpret_cast<uint4*>(gb + (g + 8) * 2048 + goff),
                   make_uint4(hw0, hw1, lw0, lw1));
        }

        if (ts < S - 1) {
            cluster_arrive();                  // release: g_hfmt stores visible
            // off-critical-path stores between arrive and wait
            float* op0 = io + (size_t)ts * BH + (size_t)orow0 * H + c0;
            float* op1 = io + (size_t)ts * BH + (size_t)(orow0 + 8) * H + c0;
            *reinterpret_cast<float2*>(op0)     = make_float2(h00, h01);
            *reinterpret_cast<float2*>(op0 + 8) = make_float2(h08, h09);
            *reinterpret_cast<float2*>(op1)     = make_float2(h20, h21);
            *reinterpret_cast<float2*>(op1 + 8) = make_float2(h28, h29);
            cluster_wait();
        } else {
            float* op0 = io + (size_t)ts * BH + (size_t)orow0 * H + c0;
            float* op1 = io + (size_t)ts * BH + (size_t)(orow0 + 8) * H + c0;
            *reinterpret_cast<float2*>(op0)     = make_float2(h00, h01);
            *reinterpret_cast<float2*>(op0 + 8) = make_float2(h08, h09);
            *reinterpret_cast<float2*>(op1)     = make_float2(h20, h21);
            *reinterpret_cast<float2*>(op1 + 8) = make_float2(h28, h29);
            float* lp0 = io + (size_t)S * BH + (size_t)orow0 * H + c0;
            float* lp1 = io + (size_t)S * BH + (size_t)(orow0 + 8) * H + c0;
            *reinterpret_cast<float2*>(lp0)     = make_float2(h00, h01);
            *reinterpret_cast<float2*>(lp0 + 8) = make_float2(h08, h09);
            *reinterpret_cast<float2*>(lp1)     = make_float2(h20, h21);
            *reinterpret_cast<float2*>(lp1 + 8) = make_float2(h28, h29);
        }
    }
}

// ===========================================================================
// kernel_launch
// Inputs: x (S,B,I), Vw (H,I), Vb (H), Ww (H,H), Wb (H)
// Output: h_seq (S,B,H) ++ h_last (B,H), fp32
// ===========================================================================
extern "C" void kernel_launch(void* const* d_in, const int* in_sizes, int n_in,
                              void* d_out, int out_size)
{
    const float* x  = (const float*)d_in[0];
    const float* Vw = (const float*)d_in[1];
    const float* Vb = (const float*)d_in[2];
    const float* Ww = (const float*)d_in[3];
    const float* Wb = (const float*)d_in[4];
    float* out = (float*)d_out;

    static bool attr_done = false;
    if (!attr_done) {
        cudaFuncSetAttribute(rnn_steps_mma,
                             cudaFuncAttributeMaxDynamicSharedMemorySize,
                             SMEM_P2);
        attr_done = true;
    }

    convert_W<<<(H * H + 255) / 256, 256>>>(Ww);

    dim3 g1(H / 128, M1 / 128);
    phase1_gemm<<<g1, 256>>>(x, Vw, Vb, out);

    dim3 g2(8, 16);   // cluster (8,1,1) via __cluster_dims__
    rnn_steps_mma<<<g2, 128, SMEM_P2>>>(Wb, out);
}

// round 8
// speedup vs baseline: 1.0917x; 1.0917x over previous
#include <cuda_runtime.h>
#include <cuda_bf16.h>
#include <math.h>
#include <stdint.h>

// Problem dims (fixed per reference)
constexpr int S = 512;
constexpr int B = 256;
constexpr int I = 512;
constexpr int H = 512;
constexpr int M1 = S * B;
constexpr int BH = B * H;

// Fragment-ready panel layout: per row, per 16-k block kb, four 16B groups:
//   [0:4) hi pair(2t,2t+1)  [4:8) hi pair(2t+8,2t+9)
//   [8:12) lo pair(2t)      [12:16) lo pair(2t+8)
// Row stride 2112 B (2112 % 128 == 64 -> conflict-free paired LDS.128).
constexpr int RSTR  = 2112;
constexpr int PANEL = 16 * RSTR;            // one A panel: 33792 B
constexpr int SM_W  = 0;                    // W panel: 64 * 2112 = 135168
constexpr int SM_A  = 64 * RSTR;            // A panels (x2) at 135168
constexpr int SM_MB = SM_A + 2 * PANEL;     // mbarriers at 202752
constexpr int SMEM_P2 = SM_MB + 32;         // 202784 bytes
// mbar offsets within SM_MB: full[b] at b*8, empty[b] at 16 + b*8

// ===========================================================================
// Static device scratch (allocation-free)
// ===========================================================================
__device__ uint32_t g_whl[H * H];           // packed {bf16 hi<<16 | bf16 lo} Ww

__device__ __forceinline__ uint32_t pack_hl(float x) {
    __nv_bfloat16 h = __float2bfloat16(x);
    float r = x - __bfloat162float(h);
    __nv_bfloat16 l = __float2bfloat16(r);
    return (((uint32_t)__bfloat16_as_ushort(h)) << 16) |
           (uint32_t)__bfloat16_as_ushort(l);
}

// split pair (a,b) into bf16 hi-word and lo-word (a in low half)
__device__ __forceinline__ void split_pair(float a, float b,
                                           uint32_t& hiw, uint32_t& low) {
    __nv_bfloat16 ah = __float2bfloat16(a), bh = __float2bfloat16(b);
    float ar = a - __bfloat162float(ah);
    float br = b - __bfloat162float(bh);
    __nv_bfloat16 al = __float2bfloat16(ar), bl = __float2bfloat16(br);
    hiw = (((uint32_t)__bfloat16_as_ushort(bh)) << 16) | __bfloat16_as_ushort(ah);
    low = (((uint32_t)__bfloat16_as_ushort(bl)) << 16) | __bfloat16_as_ushort(al);
}

__global__ void __launch_bounds__(256) convert_W(const float* __restrict__ Ww) {
    int i = blockIdx.x * blockDim.x + threadIdx.x;
    if (i < H * H) g_whl[i] = pack_hl(Ww[i]);
}

// ===========================================================================
// PTX helpers (all base sm_90 features — safe on plain sm_103 target)
// ===========================================================================
__device__ __forceinline__ uint32_t smem_to_u32(const void* smem_ptr) {
    uint32_t addr;
    asm("{ .reg .u64 tmp; cvta.to.shared.u64 tmp, %1; cvt.u32.u64 %0, tmp; }"
        : "=r"(addr) : "l"(smem_ptr));
    return addr;
}
__device__ __forceinline__ uint32_t mapa_u32(uint32_t laddr, uint32_t rank) {
    uint32_t r;
    asm("mapa.shared::cluster.u32 %0, %1, %2;" : "=r"(r) : "r"(laddr), "r"(rank));
    return r;
}
#define MBARRIER_INIT(mbar, count) \
    asm volatile("mbarrier.init.shared.b64 [%0], %1;" \
        :: "r"((uint32_t)(mbar)), "r"((uint32_t)(count)) : "memory")
#define MBARRIER_EXPECT_TX(mbar, bytes) \
    asm volatile("mbarrier.arrive.expect_tx.shared.b64 _, [%0], %1;" \
        :: "r"((uint32_t)(mbar)), "r"((uint32_t)(bytes)) : "memory")
#define MBARRIER_ARRIVE_REMOTE(laddr, rank) \
    asm volatile( \
        "{\n\t.reg .b32 remAddr;\n\t" \
        "mapa.shared::cluster.u32 remAddr, %0, %1;\n\t" \
        "mbarrier.arrive.shared::cluster.b64 _, [remAddr];\n\t}" \
        :: "r"((uint32_t)(laddr)), "r"((uint32_t)(rank)) : "memory")
// parity wait, cluster-scope acquire (orders peer st.async data before our LDS)
#define MBARRIER_WAIT_PARITY_CL(mbar_smem_addr, phase_parity) do { \
    uint32_t _mbar = (uint32_t)(mbar_smem_addr); \
    uint32_t _parity = (uint32_t)(phase_parity); \
    uint32_t _done; \
    asm volatile( \
        "{\n\t.reg .pred p;\n\t" \
        "mbarrier.try_wait.parity.acquire.cluster.shared::cta.b64 p, [%1], %2;\n\t" \
        "selp.b32 %0, 1, 0, p;\n\t}" \
        : "=r"(_done) : "r"(_mbar), "r"(_parity) : "memory"); \
    if (!_done) { \
        asm volatile( \
            "{\n\t.reg .pred P1;\n\t" \
            "WAIT_LOOP_%=:\n\t" \
            "mbarrier.try_wait.parity.acquire.cluster.shared::cta.b64 P1, [%0], %1, 0x989680;\n\t" \
            "@P1 bra.uni WAIT_DONE_%=;\n\t" \
            "bra.uni WAIT_LOOP_%=;\n\t" \
            "WAIT_DONE_%=:\n\t}" \
            :: "r"(_mbar), "r"(_parity) : "memory"); \
    } \
} while(0)
// st.async 16B to peer smem, tracked by peer's mbarrier (complete_tx bytes)
__device__ __forceinline__ void st_async_v4(uint32_t raddr, uint4 v, uint32_t rmbar) {
    asm volatile(
        "st.async.shared::cluster.mbarrier::complete_tx::bytes.v4.b32 "
        "[%0], {%1,%2,%3,%4}, [%5];"
        :: "r"(raddr), "r"(v.x), "r"(v.y), "r"(v.z), "r"(v.w), "r"(rmbar)
        : "memory");
}
__device__ __forceinline__ void cluster_sync() {
    asm volatile("barrier.cluster.arrive.aligned;" ::: "memory");
    asm volatile("barrier.cluster.wait.aligned;" ::: "memory");
}

// mma.sync m16n8k16 bf16
__device__ __forceinline__ void mma_bf16(float c[4],
                                         uint32_t a0, uint32_t a1,
                                         uint32_t a2, uint32_t a3,
                                         uint32_t b0, uint32_t b1) {
    asm volatile(
        "mma.sync.aligned.m16n8k16.row.col.f32.bf16.bf16.f32 "
        "{%0,%1,%2,%3}, {%4,%5,%6,%7}, {%8,%9}, {%0,%1,%2,%3};"
        : "+f"(c[0]), "+f"(c[1]), "+f"(c[2]), "+f"(c[3])
        : "r"(a0), "r"(a1), "r"(a2), "r"(a3), "r"(b0), "r"(b1));
}

// ===========================================================================
// Phase 1: xV = x @ Vw^T + Vb  (fp32 SIMT, known-good)
// ===========================================================================
__global__ void __launch_bounds__(256) phase1_gemm(
    const float* __restrict__ A,
    const float* __restrict__ W,
    const float* __restrict__ bias,
    float* __restrict__ C)
{
    constexpr int BM = 128, BN = 128, BK = 16;
    constexpr int K = I;
    constexpr int PAD = 4;
    __shared__ float As[BK][BM + PAD];
    __shared__ float Bs[BK][BN + PAD];

    const int tid = threadIdx.x;
    const int bn = blockIdx.x;
    const int bm = blockIdx.y;

    const float* Ap = A + (size_t)bm * BM * K;
    const float* Wp = W + (size_t)bn * BN * K;

    const int ty = tid / 16;
    const int tx = tid % 16;

    float acc[8][8];
    #pragma unroll
    for (int i = 0; i < 8; i++)
        #pragma unroll
        for (int j = 0; j < 8; j++) acc[i][j] = 0.0f;

    for (int k0 = 0; k0 < K; k0 += BK) {
        #pragma unroll
        for (int l = 0; l < 2; l++) {
            int f   = tid + l * 256;
            int row = f >> 2;
            int c4  = (f & 3) * 4;
            float4 av = *reinterpret_cast<const float4*>(Ap + (size_t)row * K + k0 + c4);
            As[c4 + 0][row] = av.x; As[c4 + 1][row] = av.y;
            As[c4 + 2][row] = av.z; As[c4 + 3][row] = av.w;
            float4 bv = *reinterpret_cast<const float4*>(Wp + (size_t)row * K + k0 + c4);
            Bs[c4 + 0][row] = bv.x; Bs[c4 + 1][row] = bv.y;
            Bs[c4 + 2][row] = bv.z; Bs[c4 + 3][row] = bv.w;
        }
        __syncthreads();
        #pragma unroll
        for (int k = 0; k < BK; k++) {
            float ar[8], br[8];
            *reinterpret_cast<float4*>(ar)     = *reinterpret_cast<const float4*>(&As[k][ty * 8]);
            *reinterpret_cast<float4*>(ar + 4) = *reinterpret_cast<const float4*>(&As[k][ty * 8 + 4]);
            *reinterpret_cast<float4*>(br)     = *reinterpret_cast<const float4*>(&Bs[k][tx * 8]);
            *reinterpret_cast<float4*>(br + 4) = *reinterpret_cast<const float4*>(&Bs[k][tx * 8 + 4]);
            #pragma unroll
            for (int i = 0; i < 8; i++)
                #pragma unroll
                for (int j = 0; j < 8; j++)
                    acc[i][j] = fmaf(ar[i], br[j], acc[i][j]);
        }
        __syncthreads();
    }
    const int rowb = bm * BM + ty * 8;
    const int colb = bn * BN + tx * 8;
    float bvals[8];
    #pragma unroll
    for (int j = 0; j < 8; j++) bvals[j] = bias[colb + j];
    #pragma unroll
    for (int i = 0; i < 8; i++) {
        float* cp = C + (size_t)(rowb + i) * H + colb;
        float4 v0, v1;
        v0.x = acc[i][0] + bvals[0]; v0.y = acc[i][1] + bvals[1];
        v0.z = acc[i][2] + bvals[2]; v0.w = acc[i][3] + bvals[3];
        v1.x = acc[i][4] + bvals[4]; v1.y = acc[i][5] + bvals[5];
        v1.z = acc[i][6] + bvals[6]; v1.w = acc[i][7] + bvals[7];
        *reinterpret_cast<float4*>(cp)     = v0;
        *reinterpret_cast<float4*>(cp + 4) = v1;
    }
}

// ===========================================================================
// Phase 2: persistent mma.sync bf16x3 recurrence; h exchanged via DSMEM
// st.async into double-buffered smem A-panels, tracked by mbarriers.
// Grid (bn=8, bm=16) = 128 CTAs; cluster (8,1,1) = one bm row group.
// CTA tile 16(M) x 64(N); 128 threads, 4 warps (warp ni: n16 slice).
// ===========================================================================
__global__ void __launch_bounds__(128, 1) __cluster_dims__(8, 1, 1)
rnn_steps_dsmem(const float* __restrict__ Wb, float* __restrict__ io)
{
    extern __shared__ char smem[];
    const uint32_t sbase = smem_to_u32(smem);

    const int tid  = threadIdx.x;
    const int wid  = tid >> 5;
    const int lane = tid & 31;
    const int bn   = blockIdx.x;               // 0..7  (cluster rank)
    const int bm   = blockIdx.y;               // 0..15
    const int Rg0  = bm * 16;
    const int cg0  = bn * 64;

    const int n0 = wid * 16;
    const int g  = lane >> 2;                  // 0..7
    const int t  = lane & 3;                   // 0..3

    // ---- Format resident W panel (rows = out cols cg0..cg0+63) ----
    for (int l = 0; l < 64; l++) {
        int j  = tid + (l << 7);               // 0..8191
        int r  = j >> 7;                       // 0..63
        int k4 = (j & 127) * 4;                // 0..508
        uint4 v = *reinterpret_cast<const uint4*>(
            &g_whl[(size_t)(cg0 + r) * 512 + k4]);
        uint32_t hi0 = __byte_perm(v.x, v.y, 0x7632);
        uint32_t lo0 = __byte_perm(v.x, v.y, 0x5410);
        uint32_t hi1 = __byte_perm(v.z, v.w, 0x7632);
        uint32_t lo1 = __byte_perm(v.z, v.w, 0x5410);
        int kb   = k4 >> 4;
        int rem  = k4 & 15;
        int slot = (rem >= 8) ? 4 : 0;
        int t0   = (rem & 7) >> 1;
        char* base = smem + SM_W + r * RSTR + kb * 64 + t0 * 16 + slot;
        *reinterpret_cast<uint32_t*>(base)      = hi0;
        *reinterpret_cast<uint32_t*>(base + 8)  = lo0;
        *reinterpret_cast<uint32_t*>(base + 16) = hi1;
        *reinterpret_cast<uint32_t*>(base + 24) = lo1;
    }

    // ---- mbarrier init: full[b] count=1 (+32KB tx), empty[b] count=8 ----
    if (tid == 0) {
        MBARRIER_INIT(sbase + SM_MB + 0, 1);   // full[0]
        MBARRIER_INIT(sbase + SM_MB + 8, 1);   // full[1]
        MBARRIER_INIT(sbase + SM_MB + 16, 8);  // empty[0]
        MBARRIER_INIT(sbase + SM_MB + 24, 8);  // empty[1]
        MBARRIER_EXPECT_TX(sbase + SM_MB + 0, 32768);  // phase 0 of full[0]
        MBARRIER_EXPECT_TX(sbase + SM_MB + 8, 32768);  // phase 0 of full[1]
    }
    __syncthreads();
    cluster_sync();                            // barriers visible cluster-wide

    // peer smem bases (mapa is linear in the offset)
    uint32_t remBase[8];
    #pragma unroll
    for (int r = 0; r < 8; r++) remBase[r] = mapa_u32(sbase, (uint32_t)r);

    // per-lane coords
    const int orow0 = Rg0 + g;                 // and +8
    const int c0    = cg0 + n0 + 2 * t;        // cols c0,c0+1 and +8,+9
    const float2 wbA = *reinterpret_cast<const float2*>(Wb + c0);
    const float2 wbB = *reinterpret_cast<const float2*>(Wb + c0 + 8);
    const int goff  = ((cg0 + n0) >> 4) * 64 + t * 16;  // granule offset in row

    // fragment base offsets (A panel picked per step by pb)
    const char* bB = smem + SM_W + (n0 + g) * RSTR + t * 16;

    int fullP0 = 0, fullP1 = 0;                // full[b] wait parities
    int emptyP0 = 1, emptyP1 = 1;              // empty[b] wait parities (pass 1st)

    // ---- t = 0 : h_0 = tanh(xV_0 + Wb); distribute via st.async ----
    {
        const float* iot = io;
        float2 xa0 = __ldcg(reinterpret_cast<const float2*>(iot + (size_t)orow0 * H + c0));
        float2 xa1 = __ldcg(reinterpret_cast<const float2*>(iot + (size_t)orow0 * H + c0 + 8));
        float2 xb0 = __ldcg(reinterpret_cast<const float2*>(iot + (size_t)(orow0 + 8) * H + c0));
        float2 xb1 = __ldcg(reinterpret_cast<const float2*>(iot + (size_t)(orow0 + 8) * H + c0 + 8));
        float h00 = tanhf(xa0.x + wbA.x), h01 = tanhf(xa0.y + wbA.y);
        float h08 = tanhf(xa1.x + wbB.x), h09 = tanhf(xa1.y + wbB.y);
        float h20 = tanhf(xb0.x + wbA.x), h21 = tanhf(xb0.y + wbA.y);
        float h28 = tanhf(xb1.x + wbB.x), h29 = tanhf(xb1.y + wbB.y);

        uint4 gr0, gr1;
        split_pair(h00, h01, gr0.x, gr0.z); split_pair(h08, h09, gr0.y, gr0.w);
        split_pair(h20, h21, gr1.x, gr1.z); split_pair(h28, h29, gr1.y, gr1.w);

        // producer: buffer 0 (first empty-wait passes by parity trick)
        MBARRIER_WAIT_PARITY_CL(sbase + SM_MB + 16, emptyP0); emptyP0 ^= 1;
        const uint32_t L0 = SM_A + g * RSTR + goff;
        #pragma unroll
        for (int r = 0; r < 8; r++) {
            uint32_t rb = remBase[r];
            st_async_v4(rb + L0,            gr0, rb + SM_MB + 0);
            st_async_v4(rb + L0 + 8 * RSTR, gr1, rb + SM_MB + 0);
        }

        float* op0 = io + (size_t)orow0 * H + c0;
        float* op1 = io + (size_t)(orow0 + 8) * H + c0;
        *reinterpret_cast<float2*>(op0)     = make_float2(h00, h01);
        *reinterpret_cast<float2*>(op0 + 8) = make_float2(h08, h09);
        *reinterpret_cast<float2*>(op1)     = make_float2(h20, h21);
        *reinterpret_cast<float2*>(op1 + 8) = make_float2(h28, h29);
    }

    // ---- steps 1 .. S-1 ----
    for (int ts = 1; ts < S; ++ts) {
        const int pb = (ts - 1) & 1;
        const int cb = ts & 1;

        // xV prefetch (independent of h_{t-1})
        const float* iot = io + (size_t)ts * BH;
        float2 xa0 = __ldcg(reinterpret_cast<const float2*>(iot + (size_t)orow0 * H + c0));
        float2 xa1 = __ldcg(reinterpret_cast<const float2*>(iot + (size_t)orow0 * H + c0 + 8));
        float2 xb0 = __ldcg(reinterpret_cast<const float2*>(iot + (size_t)(orow0 + 8) * H + c0));
        float2 xb1 = __ldcg(reinterpret_cast<const float2*>(iot + (size_t)(orow0 + 8) * H + c0 + 8));

        // consumer: wait h_{t-1} panel complete (32KB from 8 producers)
        if (pb == 0) { MBARRIER_WAIT_PARITY_CL(sbase + SM_MB + 0, fullP0); fullP0 ^= 1; }
        else         { MBARRIER_WAIT_PARITY_CL(sbase + SM_MB + 8, fullP1); fullP1 ^= 1; }

        // MMA over 32 k-blocks from panel pb
        const char* aP = smem + SM_A + pb * PANEL + g * RSTR + t * 16;
        float chh0[4] = {0.f,0.f,0.f,0.f}, chl0[4] = {0.f,0.f,0.f,0.f}, clh0[4] = {0.f,0.f,0.f,0.f};
        float chh1[4] = {0.f,0.f,0.f,0.f}, chl1[4] = {0.f,0.f,0.f,0.f}, clh1[4] = {0.f,0.f,0.f,0.f};
        #pragma unroll 8
        for (int kb = 0; kb < 32; ++kb) {
            uint4 A1 = *reinterpret_cast<const uint4*>(aP + kb * 64);
            uint4 A2 = *reinterpret_cast<const uint4*>(aP + 8 * RSTR + kb * 64);
            uint4 B1 = *reinterpret_cast<const uint4*>(bB + kb * 64);
            uint4 B2 = *reinterpret_cast<const uint4*>(bB + 8 * RSTR + kb * 64);
            mma_bf16(chh0, A1.x, A2.x, A1.y, A2.y, B1.x, B1.y);
            mma_bf16(chh1, A1.x, A2.x, A1.y, A2.y, B2.x, B2.y);
            mma_bf16(chl0, A1.x, A2.x, A1.y, A2.y, B1.z, B1.w);
            mma_bf16(chl1, A1.x, A2.x, A1.y, A2.y, B2.z, B2.w);
            mma_bf16(clh0, A1.z, A2.z, A1.w, A2.w, B1.x, B1.y);
            mma_bf16(clh1, A1.z, A2.z, A1.w, A2.w, B2.x, B2.y);
        }
        __syncthreads();                       // all warps done reading panel pb

        if (tid == 0 && ts <= S - 3) {
            // re-arm full[pb] for its next phase (writes at step ts+1)
            MBARRIER_EXPECT_TX(sbase + SM_MB + pb * 8, 32768);
            // free panel pb: arrive on every cluster CTA's empty[pb]
            const uint32_t eoff = sbase + SM_MB + 16 + pb * 8;
            #pragma unroll
            for (int r = 0; r < 8; r++) MBARRIER_ARRIVE_REMOTE(eoff, r);
        }

        // epilogue: h = tanh(acc + xV + Wb)
        float h00 = tanhf(chh0[0] + chl0[0] + clh0[0] + xa0.x + wbA.x);
        float h01 = tanhf(chh0[1] + chl0[1] + clh0[1] + xa0.y + wbA.y);
        float h08 = tanhf(chh1[0] + chl1[0] + clh1[0] + xa1.x + wbB.x);
        float h09 = tanhf(chh1[1] + chl1[1] + clh1[1] + xa1.y + wbB.y);
        float h20 = tanhf(chh0[2] + chl0[2] + clh0[2] + xb0.x + wbA.x);
        float h21 = tanhf(chh0[3] + chl0[3] + clh0[3] + xb0.y + wbA.y);
        float h28 = tanhf(chh1[2] + chl1[2] + clh1[2] + xb1.x + wbB.x);
        float h29 = tanhf(chh1[3] + chl1[3] + clh1[3] + xb1.y + wbB.y);

        if (ts <= S - 2) {
            // producer: wait panel cb free, push granules to all 8 peers
            uint4 gr0, gr1;
            split_pair(h00, h01, gr0.x, gr0.z); split_pair(h08, h09, gr0.y, gr0.w);
            split_pair(h20, h21, gr1.x, gr1.z); split_pair(h28, h29, gr1.y, gr1.w);
            if (cb == 0) { MBARRIER_WAIT_PARITY_CL(sbase + SM_MB + 16, emptyP0); emptyP0 ^= 1; }
            else         { MBARRIER_WAIT_PARITY_CL(sbase + SM_MB + 24, emptyP1); emptyP1 ^= 1; }
            const uint32_t L0 = SM_A + cb * PANEL + g * RSTR + goff;
            #pragma unroll
            for (int r = 0; r < 8; r++) {
                uint32_t rb = remBase[r];
                st_async_v4(rb + L0,            gr0, rb + SM_MB + cb * 8);
                st_async_v4(rb + L0 + 8 * RSTR, gr1, rb + SM_MB + cb * 8);
            }
        }

        // h_seq outputs (off critical path)
        float* op0 = io + (size_t)ts * BH + (size_t)orow0 * H + c0;
        float* op1 = io + (size_t)ts * BH + (size_t)(orow0 + 8) * H + c0;
        *reinterpret_cast<float2*>(op0)     = make_float2(h00, h01);
        *reinterpret_cast<float2*>(op0 + 8) = make_float2(h08, h09);
        *reinterpret_cast<float2*>(op1)     = make_float2(h20, h21);
        *reinterpret_cast<float2*>(op1 + 8) = make_float2(h28, h29);
        if (ts == S - 1) {
            float* lp0 = io + (size_t)S * BH + (size_t)orow0 * H + c0;
            float* lp1 = io + (size_t)S * BH + (size_t)(orow0 + 8) * H + c0;
            *reinterpret_cast<float2*>(lp0)     = make_float2(h00, h01);
            *reinterpret_cast<float2*>(lp0 + 8) = make_float2(h08, h09);
            *reinterpret_cast<float2*>(lp1)     = make_float2(h20, h21);
            *reinterpret_cast<float2*>(lp1 + 8) = make_float2(h28, h29);
        }
    }

    // no CTA may exit while peers' remote ops could target its smem
    cluster_sync();
}

// ===========================================================================
// kernel_launch
// Inputs: x (S,B,I), Vw (H,I), Vb (H), Ww (H,H), Wb (H)
// Output: h_seq (S,B,H) ++ h_last (B,H), fp32
// ===========================================================================
extern "C" void kernel_launch(void* const* d_in, const int* in_sizes, int n_in,
                              void* d_out, int out_size)
{
    const float* x  = (const float*)d_in[0];
    const float* Vw = (const float*)d_in[1];
    const float* Vb = (const float*)d_in[2];
    const float* Ww = (const float*)d_in[3];
    const float* Wb = (const float*)d_in[4];
    float* out = (float*)d_out;

    static bool attr_done = false;
    if (!attr_done) {
        cudaFuncSetAttribute(rnn_steps_dsmem,
                             cudaFuncAttributeMaxDynamicSharedMemorySize,
                             SMEM_P2);
        attr_done = true;
    }

    convert_W<<<(H * H + 255) / 256, 256>>>(Ww);

    dim3 g1(H / 128, M1 / 128);
    phase1_gemm<<<g1, 256>>>(x, Vw, Vb, out);

    dim3 g2(8, 16);   // cluster (8,1,1) via __cluster_dims__
    rnn_steps_dsmem<<<g2, 128, SMEM_P2>>>(Wb, out);
}

// round 10
// speedup vs baseline: 1.4542x; 1.3320x over previous
#include <cuda_runtime.h>
#include <cuda_bf16.h>
#include <math.h>
#include <stdint.h>

// Problem dims (fixed per reference)
constexpr int S = 512;
constexpr int B = 256;
constexpr int I = 512;
constexpr int H = 512;
constexpr int M1 = S * B;
constexpr int BH = B * H;

// Fragment-ready panel layout: per row, per 16-k block kb, four 16B groups:
//   [0:4) hi(2t,2t+1) [4:8) hi(2t+8,2t+9) [8:12) lo(2t) [12:16) lo(2t+8)
// Row stride 2112 B (2112 % 128 == 64 -> conflict-free LDS.128 per quad-phase).
constexpr int RSTR = 2112;
constexpr int RU4  = 132;
constexpr int SM_W = 0;                    // rnn W panel: 32*2112 = 67584
constexpr int SM_A = 32 * RSTR;            // rnn A panel
constexpr int SMEM_P2 = 2 * 32 * RSTR;     // 135168

// Phase-1 GEMM smem layout
constexpr int RA      = 320;               // A chunk row stride (320%128==64)
constexpr int P1_SM_B = 0;                 // B panel: 64*2112 = 135168
constexpr int P1_SM_A = 64 * RSTR;         // A bufs at 135168 (+b*40960)
constexpr int P1_ABUF = 128 * RA;          // 40960
constexpr int P1_SMEM = P1_SM_A + 2 * P1_ABUF;   // 217088

// ===========================================================================
// Static device scratch (allocation-free). NOTE: these symbols must ONLY be
// referenced from device code (host-side use would bind the host shadow).
// ===========================================================================
__device__ uint4 g_hfmt[2][8][32 * RU4];   // h in fragment-ready format (rnn)
__device__ uint32_t g_whl[H * H];          // packed {bf16 hi<<16 | lo} of Ww
__device__ unsigned int g_bar[8];          // per-bm-group barrier counters
__device__ uint4 g_xfmt[(size_t)M1 * 128]; // x  fragment-format (row: 128 u4)
__device__ uint4 g_vfmt[(size_t)H * 128];  // Vw fragment-format

__device__ __forceinline__ uint32_t pack_hl(float x) {
    __nv_bfloat16 h = __float2bfloat16(x);
    float r = x - __bfloat162float(h);
    __nv_bfloat16 l = __float2bfloat16(r);
    return (((uint32_t)__bfloat16_as_ushort(h)) << 16) |
           (uint32_t)__bfloat16_as_ushort(l);
}
__device__ __forceinline__ void split_pair(float a, float b,
                                           uint32_t& hiw, uint32_t& low) {
    __nv_bfloat16 ah = __float2bfloat16(a), bh = __float2bfloat16(b);
    float ar = a - __bfloat162float(ah);
    float br = b - __bfloat162float(bh);
    __nv_bfloat16 al = __float2bfloat16(ar), bl = __float2bfloat16(br);
    hiw = (((uint32_t)__bfloat16_as_ushort(bh)) << 16) | __bfloat16_as_ushort(ah);
    low = (((uint32_t)__bfloat16_as_ushort(bl)) << 16) | __bfloat16_as_ushort(al);
}

__global__ void reset_ctr() {
    if (threadIdx.x < 8) g_bar[threadIdx.x] = 0u;
}

__global__ void __launch_bounds__(256) convert_W(const float* __restrict__ Ww) {
    int i = blockIdx.x * blockDim.x + threadIdx.x;
    if (i < H * H) g_whl[i] = pack_hl(Ww[i]);
}

// Pack a row-major fp32 matrix (512 cols) into fragment-format rows of
// 128 uint4 (32 kb-blocks x 64B). One thread per kb-block (16 elements).
// Device-symbol destinations referenced INSIDE device code.
__device__ __forceinline__ void pack_row_block(const float* __restrict__ src,
                                               uint4* __restrict__ dst,
                                               int idx) {
    int m  = idx >> 5;
    int kb = idx & 31;
    const float* sp = src + (size_t)m * 512 + kb * 16;
    float e[16];
    #pragma unroll
    for (int q = 0; q < 4; q++) {
        float4 v = *reinterpret_cast<const float4*>(sp + q * 4);
        e[q * 4 + 0] = v.x; e[q * 4 + 1] = v.y;
        e[q * 4 + 2] = v.z; e[q * 4 + 3] = v.w;
    }
    uint4* dp = dst + (size_t)m * 128 + kb * 4;
    #pragma unroll
    for (int t = 0; t < 4; t++) {
        uint4 o;
        uint32_t loA, loB;
        split_pair(e[2 * t],     e[2 * t + 1], o.x, loA);
        split_pair(e[2 * t + 8], e[2 * t + 9], o.y, loB);
        o.z = loA; o.w = loB;
        dp[t] = o;
    }
}

__global__ void __launch_bounds__(256) pack_x(const float* __restrict__ src) {
    int idx = blockIdx.x * blockDim.x + threadIdx.x;
    if (idx < M1 * 32) pack_row_block(src, g_xfmt, idx);
}
__global__ void __launch_bounds__(256) pack_v(const float* __restrict__ src) {
    int idx = blockIdx.x * blockDim.x + threadIdx.x;
    if (idx < H * 32) pack_row_block(src, g_vfmt, idx);
}

// ===========================================================================
// Barrier primitives (no membar.gl -> no L1 flush)
// ===========================================================================
__device__ __forceinline__ void bar_arrive(unsigned int* p) {
    asm volatile("red.release.gpu.add.u32 [%0], 1;" :: "l"(p) : "memory");
}
__device__ __forceinline__ unsigned int bar_peek(const unsigned int* p) {
    unsigned int v;
    asm volatile("ld.acquire.gpu.u32 %0, [%1];" : "=r"(v) : "l"(p) : "memory");
    return v;
}

// ===========================================================================
// mma.sync m16n8k16 bf16 + cp.async helpers
// ===========================================================================
__device__ __forceinline__ void mma_bf16(float c[4],
                                         uint32_t a0, uint32_t a1,
                                         uint32_t a2, uint32_t a3,
                                         uint32_t b0, uint32_t b1) {
    asm volatile(
        "mma.sync.aligned.m16n8k16.row.col.f32.bf16.bf16.f32 "
        "{%0,%1,%2,%3}, {%4,%5,%6,%7}, {%8,%9}, {%0,%1,%2,%3};"
        : "+f"(c[0]), "+f"(c[1]), "+f"(c[2]), "+f"(c[3])
        : "r"(a0), "r"(a1), "r"(a2), "r"(a3), "r"(b0), "r"(b1));
}
__device__ __forceinline__ uint32_t smem_to_u32(const void* p) {
    uint32_t a;
    asm("{ .reg .u64 t; cvta.to.shared.u64 t, %1; cvt.u32.u64 %0, t; }"
        : "=r"(a) : "l"(p));
    return a;
}
__device__ __forceinline__ void cp16(uint32_t dst, const void* src) {
    asm volatile("cp.async.cg.shared.global [%0], [%1], 16;"
                 :: "r"(dst), "l"(src));
}
__device__ __forceinline__ void cp_commit() {
    asm volatile("cp.async.commit_group;");
}
template <int N>
__device__ __forceinline__ void cp_wait() {
    asm volatile("cp.async.wait_group %0;" :: "n"(N));
}

// ===========================================================================
// Phase 1: xV = x @ Vw^T + Vb via bf16x3 mma.sync.
// Grid (bn=8, bm=1024). CTA tile 128(M)x64(N), 256 thr, 8 warps (4m x 2n),
// warp tile m32xn32 (24 HMMA per kb). Vw panel smem-resident full-k;
// A (x) double-buffered k64 chunks via cp.async.
// ===========================================================================
__global__ void __launch_bounds__(256, 1) phase1_mma(
    const float* __restrict__ Vb, float* __restrict__ C)
{
    extern __shared__ char smem[];
    const uint32_t sbase = smem_to_u32(smem);

    const int tid  = threadIdx.x;
    const int wid  = tid >> 5;
    const int lane = tid & 31;
    const int bn   = blockIdx.x;           // 0..7
    const int bm   = blockIdx.y;           // 0..1023
    const int mi   = wid >> 1;             // 0..3
    const int ni   = wid & 1;              // 0..1
    const int m0   = mi * 32;
    const int n0   = ni * 32;
    const int g    = lane >> 2;
    const int t    = lane & 3;

    // ---- B panel (Vw rows bn*64..+64, full k) via cp.async ----
    {
        const uint4* vsrc = g_vfmt + (size_t)(bn * 64) * 128;
        #pragma unroll
        for (int i = 0; i < 32; i++) {
            int j = tid + i * 256;         // 0..8191
            int r = j >> 7;
            int u = j & 127;
            cp16(sbase + P1_SM_B + r * RSTR + u * 16, vsrc + (size_t)r * 128 + u);
        }
    }
    // ---- A chunk 0 and 1 ----
    const uint4* xsrc = g_xfmt + (size_t)(bm * 128) * 128;
    #pragma unroll
    for (int i = 0; i < 8; i++) {
        int j = tid + i * 256;             // 0..2047
        int r = j >> 4;
        int u = j & 15;
        cp16(sbase + P1_SM_A + r * RA + u * 16, xsrc + (size_t)r * 128 + u);
    }
    cp_commit();                           // group: B + chunk0
    #pragma unroll
    for (int i = 0; i < 8; i++) {
        int j = tid + i * 256;
        int r = j >> 4;
        int u = j & 15;
        cp16(sbase + P1_SM_A + P1_ABUF + r * RA + u * 16,
             xsrc + (size_t)r * 128 + 16 + u);
    }
    cp_commit();                           // group: chunk1

    float chh[2][4][4], chl[2][4][4], clh[2][4][4];
    #pragma unroll
    for (int a = 0; a < 2; a++)
        #pragma unroll
        for (int b = 0; b < 4; b++)
            #pragma unroll
            for (int c = 0; c < 4; c++) {
                chh[a][b][c] = 0.f; chl[a][b][c] = 0.f; clh[a][b][c] = 0.f;
            }

    const char* aBase = smem + P1_SM_A + (m0 + g) * RA + t * 16;
    const char* bBase = smem + P1_SM_B + (n0 + g) * RSTR + t * 16;

    #pragma unroll 1
    for (int c = 0; c < 8; ++c) {
        if (c < 7) cp_wait<1>(); else cp_wait<0>();
        __syncthreads();

        const char* aC = aBase + (c & 1) * P1_ABUF;
        #pragma unroll
        for (int kb2 = 0; kb2 < 4; kb2++) {
            uint4 A1 = *reinterpret_cast<const uint4*>(aC + kb2 * 64);
            uint4 A2 = *reinterpret_cast<const uint4*>(aC + 8 * RA + kb2 * 64);
            uint4 A3 = *reinterpret_cast<const uint4*>(aC + 16 * RA + kb2 * 64);
            uint4 A4 = *reinterpret_cast<const uint4*>(aC + 24 * RA + kb2 * 64);
            const char* bC = bBase + (c * 4 + kb2) * 64;
            uint4 Bv[4];
            Bv[0] = *reinterpret_cast<const uint4*>(bC);
            Bv[1] = *reinterpret_cast<const uint4*>(bC + 8 * RSTR);
            Bv[2] = *reinterpret_cast<const uint4*>(bC + 16 * RSTR);
            Bv[3] = *reinterpret_cast<const uint4*>(bC + 24 * RSTR);
            #pragma unroll
            for (int nj = 0; nj < 4; nj++) {
                mma_bf16(chh[0][nj], A1.x, A2.x, A1.y, A2.y, Bv[nj].x, Bv[nj].y);
                mma_bf16(chl[0][nj], A1.x, A2.x, A1.y, A2.y, Bv[nj].z, Bv[nj].w);
                mma_bf16(clh[0][nj], A1.z, A2.z, A1.w, A2.w, Bv[nj].x, Bv[nj].y);
                mma_bf16(chh[1][nj], A3.x, A4.x, A3.y, A4.y, Bv[nj].x, Bv[nj].y);
                mma_bf16(chl[1][nj], A3.x, A4.x, A3.y, A4.y, Bv[nj].z, Bv[nj].w);
                mma_bf16(clh[1][nj], A3.z, A4.z, A3.w, A4.w, Bv[nj].x, Bv[nj].y);
            }
        }
        __syncthreads();                   // buffer (c&1)^1 free for refill

        if (c + 2 < 8) {
            const int nb = (c + 2) & 1;
            #pragma unroll
            for (int i = 0; i < 8; i++) {
                int j = tid + i * 256;
                int r = j >> 4;
                int u = j & 15;
                cp16(sbase + P1_SM_A + nb * P1_ABUF + r * RA + u * 16,
                     xsrc + (size_t)r * 128 + (c + 2) * 16 + u);
            }
            cp_commit();
        }
    }

    // ---- epilogue: sum products, add bias, store fp32 ----
    #pragma unroll
    for (int mt = 0; mt < 2; mt++) {
        #pragma unroll
        for (int nj = 0; nj < 4; nj++) {
            const int col = bn * 64 + n0 + nj * 8 + 2 * t;
            const float2 bias = *reinterpret_cast<const float2*>(Vb + col);
            const int row0 = bm * 128 + m0 + mt * 16 + g;
            float s0 = chh[mt][nj][0] + chl[mt][nj][0] + clh[mt][nj][0] + bias.x;
            float s1 = chh[mt][nj][1] + chl[mt][nj][1] + clh[mt][nj][1] + bias.y;
            float s2 = chh[mt][nj][2] + chl[mt][nj][2] + clh[mt][nj][2] + bias.x;
            float s3 = chh[mt][nj][3] + chl[mt][nj][3] + clh[mt][nj][3] + bias.y;
            *reinterpret_cast<float2*>(C + (size_t)row0 * H + col) =
                make_float2(s0, s1);
            *reinterpret_cast<float2*>(C + (size_t)(row0 + 8) * H + col) =
                make_float2(s2, s3);
        }
    }
}

// ===========================================================================
// Phase 2: persistent mma.sync bf16x3 recurrence (R5 structure, proven).
// Grid: 128 CTAs = bm(0..7) x bn(0..15); tile 32(M) x 32(N); 128 threads.
// 4 warps: mi = wid>>1 (m0=16*mi), ni = wid&1 (n0=16*ni) -> m16n16 each.
// ===========================================================================
__global__ void __launch_bounds__(128, 1) rnn_steps_mma(
    const float* __restrict__ Wb,
    float* __restrict__ io)
{
    extern __shared__ char smem[];

    const int tid  = threadIdx.x;
    const int wid  = tid >> 5;
    const int lane = tid & 31;
    const int bm   = blockIdx.x >> 4;          // 0..7
    const int bn   = blockIdx.x & 15;          // 0..15
    const int Rg0  = bm * 32;
    const int cg0  = bn * 32;

    const int mi = wid >> 1;
    const int ni = wid & 1;
    const int m0 = mi * 16;
    const int n0 = ni * 16;
    const int g  = lane >> 2;
    const int t  = lane & 3;

    // ---- Format resident W panel once (rows = out cols cg0..cg0+31) ----
    for (int l = 0; l < 32; l++) {
        int j  = tid + (l << 7);
        int r  = j >> 7;
        int k4 = (j & 127) * 4;
        uint4 v = *reinterpret_cast<const uint4*>(
            &g_whl[(size_t)(cg0 + r) * 512 + k4]);
        uint32_t hi0 = __byte_perm(v.x, v.y, 0x7632);
        uint32_t lo0 = __byte_perm(v.x, v.y, 0x5410);
        uint32_t hi1 = __byte_perm(v.z, v.w, 0x7632);
        uint32_t lo1 = __byte_perm(v.z, v.w, 0x5410);
        int kb   = k4 >> 4;
        int rem  = k4 & 15;
        int slot = (rem >= 8) ? 4 : 0;
        int t0   = (rem & 7) >> 1;
        char* base = smem + SM_W + r * RSTR + kb * 64 + t0 * 16 + slot;
        *reinterpret_cast<uint32_t*>(base)      = hi0;
        *reinterpret_cast<uint32_t*>(base + 8)  = lo0;
        *reinterpret_cast<uint32_t*>(base + 16) = hi1;
        *reinterpret_cast<uint32_t*>(base + 24) = lo1;
    }

    const char* aB = smem + SM_A + (m0 + g) * RSTR + t * 16;
    const char* bB = smem + SM_W + (n0 + g) * RSTR + t * 16;

    const int orow0 = Rg0 + m0 + g;
    const int c0    = cg0 + n0 + 2 * t;
    const float2 wbA = *reinterpret_cast<const float2*>(Wb + c0);
    const float2 wbB = *reinterpret_cast<const float2*>(Wb + c0 + 8);
    const int goff = ((cg0 + n0) >> 4) * 64 + t * 16;

    // ---- t = 0 : h_0 = tanh(xV_0 + Wb) ----
    {
        const int r  = tid >> 2;
        const int c8 = (tid & 3) * 8;
        const int gr = Rg0 + r;
        const float* xvp = io + (size_t)gr * H + cg0 + c8;
        float4 xv0 = __ldcg(reinterpret_cast<const float4*>(xvp));
        float4 xv1 = __ldcg(reinterpret_cast<const float4*>(xvp + 4));
        const float4 wb0 = *reinterpret_cast<const float4*>(Wb + cg0 + c8);
        const float4 wb1 = *reinterpret_cast<const float4*>(Wb + cg0 + c8 + 4);
        float h[8];
        h[0] = tanhf(xv0.x + wb0.x); h[1] = tanhf(xv0.y + wb0.y);
        h[2] = tanhf(xv0.z + wb0.z); h[3] = tanhf(xv0.w + wb0.w);
        h[4] = tanhf(xv1.x + wb1.x); h[5] = tanhf(xv1.y + wb1.y);
        h[6] = tanhf(xv1.z + wb1.z); h[7] = tanhf(xv1.w + wb1.w);
        float* op = io + (size_t)gr * H + cg0 + c8;
        *reinterpret_cast<float4*>(op)     = make_float4(h[0], h[1], h[2], h[3]);
        *reinterpret_cast<float4*>(op + 4) = make_float4(h[4], h[5], h[6], h[7]);
        char* gbase = reinterpret_cast<char*>(&g_hfmt[0][bm][0]) + r * RSTR;
        #pragma unroll
        for (int p = 0; p < 4; p++) {
            int k   = c8 + 2 * p;
            int km  = k & 15;
            int tg  = (km & 7) >> 1;
            int sl  = (km >= 8) ? 4 : 0;
            int kb  = (cg0 + k) >> 4;
            uint32_t hiw, low;
            split_pair(h[2 * p], h[2 * p + 1], hiw, low);
            char* ptr = gbase + kb * 64 + tg * 16 + sl;
            __stcg(reinterpret_cast<uint32_t*>(ptr), hiw);
            __stcg(reinterpret_cast<uint32_t*>(ptr + 8), low);
        }
    }
    __syncthreads();
    if (tid == 0) bar_arrive(&g_bar[bm]);

    // ---- steps 1 .. S-1 ----
    for (int ts = 1; ts < S; ++ts) {
        const float* iot = io + (size_t)ts * BH;
        float2 xva0 = __ldcg(reinterpret_cast<const float2*>(iot + (size_t)orow0 * H + c0));
        float2 xva1 = __ldcg(reinterpret_cast<const float2*>(iot + (size_t)orow0 * H + c0 + 8));
        float2 xvb0 = __ldcg(reinterpret_cast<const float2*>(iot + (size_t)(orow0 + 8) * H + c0));
        float2 xvb1 = __ldcg(reinterpret_cast<const float2*>(iot + (size_t)(orow0 + 8) * H + c0 + 8));

        if (tid == 0) {
            const unsigned target = (unsigned)ts * 16u;
            while (bar_peek(&g_bar[bm]) < target) { }
        }
        __syncthreads();

        const uint4* src = &g_hfmt[(ts + 1) & 1][bm][0];
        #pragma unroll 8
        for (int l = 0; l < 32; l++) {
            int j = tid + (l << 7);
            int r = j >> 7;
            int c = j & 127;
            uint4 v = __ldcg(src + r * RU4 + c);
            *reinterpret_cast<uint4*>(smem + SM_A + r * RSTR + c * 16) = v;
        }
        __syncthreads();

        float chh0[4] = {0.f,0.f,0.f,0.f}, chl0[4] = {0.f,0.f,0.f,0.f}, clh0[4] = {0.f,0.f,0.f,0.f};
        float chh1[4] = {0.f,0.f,0.f,0.f}, chl1[4] = {0.f,0.f,0.f,0.f}, clh1[4] = {0.f,0.f,0.f,0.f};

        #pragma unroll 8
        for (int kb = 0; kb < 32; ++kb) {
            uint4 A1 = *reinterpret_cast<const uint4*>(aB + kb * 64);
            uint4 A2 = *reinterpret_cast<const uint4*>(aB + 8 * RSTR + kb * 64);
            uint4 B1 = *reinterpret_cast<const uint4*>(bB + kb * 64);
            uint4 B2 = *reinterpret_cast<const uint4*>(bB + 8 * RSTR + kb * 64);
            mma_bf16(chh0, A1.x, A2.x, A1.y, A2.y, B1.x, B1.y);
            mma_bf16(chh1, A1.x, A2.x, A1.y, A2.y, B2.x, B2.y);
            mma_bf16(chl0, A1.x, A2.x, A1.y, A2.y, B1.z, B1.w);
            mma_bf16(chl1, A1.x, A2.x, A1.y, A2.y, B2.z, B2.w);
            mma_bf16(clh0, A1.z, A2.z, A1.w, A2.w, B1.x, B1.y);
            mma_bf16(clh1, A1.z, A2.z, A1.w, A2.w, B2.x, B2.y);
        }

        float h00 = tanhf(chh0[0] + chl0[0] + clh0[0] + xva0.x + wbA.x);
        float h01 = tanhf(chh0[1] + chl0[1] + clh0[1] + xva0.y + wbA.y);
        float h08 = tanhf(chh1[0] + chl1[0] + clh1[0] + xva1.x + wbB.x);
        float h09 = tanhf(chh1[1] + chl1[1] + clh1[1] + xva1.y + wbB.y);
        float h20 = tanhf(chh0[2] + chl0[2] + clh0[2] + xvb0.x + wbA.x);
        float h21 = tanhf(chh0[3] + chl0[3] + clh0[3] + xvb0.y + wbA.y);
        float h28 = tanhf(chh1[2] + chl1[2] + clh1[2] + xvb1.x + wbB.x);
        float h29 = tanhf(chh1[3] + chl1[3] + clh1[3] + xvb1.y + wbB.y);

        float* op0 = io + (size_t)ts * BH + (size_t)orow0 * H + c0;
        float* op1 = io + (size_t)ts * BH + (size_t)(orow0 + 8) * H + c0;
        *reinterpret_cast<float2*>(op0)     = make_float2(h00, h01);
        *reinterpret_cast<float2*>(op0 + 8) = make_float2(h08, h09);
        *reinterpret_cast<float2*>(op1)     = make_float2(h20, h21);
        *reinterpret_cast<float2*>(op1 + 8) = make_float2(h28, h29);

        {
            char* gb = reinterpret_cast<char*>(&g_hfmt[ts & 1][bm][0]);
            uint32_t hw0, lw0, hw1, lw1;
            split_pair(h00, h01, hw0, lw0);
            split_pair(h08, h09, hw1, lw1);
            __stcg(reinterpret_cast<uint4*>(gb + (m0 + g) * RSTR + goff),
                   make_uint4(hw0, hw1, lw0, lw1));
            split_pair(h20, h21, hw0, lw0);
            split_pair(h28, h29, hw1, lw1);
            __stcg(reinterpret_cast<uint4*>(gb + (m0 + g + 8) * RSTR + goff),
                   make_uint4(hw0, hw1, lw0, lw1));
        }

        if (ts == S - 1) {
            float* lp0 = io + (size_t)S * BH + (size_t)orow0 * H + c0;
            float* lp1 = io + (size_t)S * BH + (size_t)(orow0 + 8) * H + c0;
            *reinterpret_cast<float2*>(lp0)     = make_float2(h00, h01);
            *reinterpret_cast<float2*>(lp0 + 8) = make_float2(h08, h09);
            *reinterpret_cast<float2*>(lp1)     = make_float2(h20, h21);
            *reinterpret_cast<float2*>(lp1 + 8) = make_float2(h28, h29);
        }

        __syncthreads();
        if (tid == 0) bar_arrive(&g_bar[bm]);
    }
}

// ===========================================================================
// kernel_launch
// Inputs: x (S,B,I), Vw (H,I), Vb (H), Ww (H,H), Wb (H)
// Output: h_seq (S,B,H) ++ h_last (B,H), fp32
// ===========================================================================
extern "C" void kernel_launch(void* const* d_in, const int* in_sizes, int n_in,
                              void* d_out, int out_size)
{
    const float* x  = (const float*)d_in[0];
    const float* Vw = (const float*)d_in[1];
    const float* Vb = (const float*)d_in[2];
    const float* Ww = (const float*)d_in[3];
    const float* Wb = (const float*)d_in[4];
    float* out = (float*)d_out;

    static bool attr_done = false;
    if (!attr_done) {
        cudaFuncSetAttribute(rnn_steps_mma,
                             cudaFuncAttributeMaxDynamicSharedMemorySize,
                             SMEM_P2);
        cudaFuncSetAttribute(phase1_mma,
                             cudaFuncAttributeMaxDynamicSharedMemorySize,
                             P1_SMEM);
        attr_done = true;
    }

    // barrier reset each launch -> deterministic across graph replays
    reset_ctr<<<1, 32>>>();

    convert_W<<<(H * H + 255) / 256, 256>>>(Ww);
    pack_x<<<(M1 * 32 + 255) / 256, 256>>>(x);
    pack_v<<<(H * 32 + 255) / 256, 256>>>(Vw);

    dim3 g1(8, 1024);
    phase1_mma<<<g1, 256, P1_SMEM>>>(Vb, out);

    rnn_steps_mma<<<128, 128, SMEM_P2>>>(Wb, out);
}

// round 11
// speedup vs baseline: 1.8972x; 1.3047x over previous
#include <cuda_runtime.h>
#include <cuda_bf16.h>
#include <math.h>
#include <stdint.h>

// Problem dims (fixed per reference)
constexpr int S = 512;
constexpr int B = 256;
constexpr int I = 512;
constexpr int H = 512;
constexpr int M1 = S * B;
constexpr int BH = B * H;

// Fragment-ready panel layout: per row, per 16-k block kb, four 16B groups:
//   [0:4) hi(2t,2t+1) [4:8) hi(2t+8,2t+9) [8:12) lo(2t) [12:16) lo(2t+8)
// Row stride 2112 B (2112 % 128 == 64 -> conflict-free LDS.128 per quad-phase).
constexpr int RSTR = 2112;
constexpr int RU4  = 132;
constexpr int SM_W = 0;                    // rnn W panel: 32*2112 = 67584
constexpr int SM_A = 32 * RSTR;            // rnn A panel
constexpr int SMEM_P2 = 2 * 32 * RSTR;     // 135168

// Phase-1 GEMM smem layout
constexpr int RA      = 320;               // A chunk row stride (320%128==64)
constexpr int P1_SM_B = 0;                 // B panel: 64*2112 = 135168
constexpr int P1_SM_A = 64 * RSTR;         // A bufs at 135168 (+b*40960)
constexpr int P1_ABUF = 128 * RA;          // 40960
constexpr int P1_SMEM = P1_SM_A + 2 * P1_ABUF;   // 217088

// ===========================================================================
// Static device scratch (allocation-free). NOTE: these symbols must ONLY be
// referenced from device code (host-side use would bind the host shadow).
// ===========================================================================
__device__ uint4 g_hfmt[2][8][32 * RU4];   // h in fragment-ready format (rnn)
__device__ uint32_t g_whl[H * H];          // packed {bf16 hi<<16 | lo} of Ww
__device__ unsigned int g_bar[8];          // per-bm-group barrier counters
__device__ uint4 g_xfmt[(size_t)M1 * 128]; // x  fragment-format (row: 128 u4)
__device__ uint4 g_vfmt[(size_t)H * 128];  // Vw fragment-format

__device__ __forceinline__ uint32_t pack_hl(float x) {
    __nv_bfloat16 h = __float2bfloat16(x);
    float r = x - __bfloat162float(h);
    __nv_bfloat16 l = __float2bfloat16(r);
    return (((uint32_t)__bfloat16_as_ushort(h)) << 16) |
           (uint32_t)__bfloat16_as_ushort(l);
}
__device__ __forceinline__ void split_pair(float a, float b,
                                           uint32_t& hiw, uint32_t& low) {
    __nv_bfloat16 ah = __float2bfloat16(a), bh = __float2bfloat16(b);
    float ar = a - __bfloat162float(ah);
    float br = b - __bfloat162float(bh);
    __nv_bfloat16 al = __float2bfloat16(ar), bl = __float2bfloat16(br);
    hiw = (((uint32_t)__bfloat16_as_ushort(bh)) << 16) | __bfloat16_as_ushort(ah);
    low = (((uint32_t)__bfloat16_as_ushort(bl)) << 16) | __bfloat16_as_ushort(al);
}
// Fast truncation split: hi = top-16 bits (exact bf16 by truncation),
// lo = rn(x - hi). 1 PRMT + 2 FADD + 1 packed CVT per pair.
__device__ __forceinline__ void split_pair_tr(float a, float b,
                                              uint32_t& hiw, uint32_t& low) {
    uint32_t au = __float_as_uint(a), bu = __float_as_uint(b);
    hiw = __byte_perm(au, bu, 0x7632);              // {b.hi16 | a.hi16}
    float ar = a - __uint_as_float(au & 0xFFFF0000u);
    float br = b - __uint_as_float(bu & 0xFFFF0000u);
    asm("cvt.rn.bf16x2.f32 %0, %1, %2;" : "=r"(low) : "f"(br), "f"(ar));
}

__global__ void reset_ctr() {
    if (threadIdx.x < 8) g_bar[threadIdx.x] = 0u;
}

__global__ void __launch_bounds__(256) convert_W(const float* __restrict__ Ww) {
    int i = blockIdx.x * blockDim.x + threadIdx.x;
    if (i < H * H) g_whl[i] = pack_hl(Ww[i]);
}

// Pack a row-major fp32 matrix (512 cols) into fragment-format rows of
// 128 uint4 (32 kb-blocks x 64B). One thread per kb-block (16 elements).
__device__ __forceinline__ void pack_row_block(const float* __restrict__ src,
                                               uint4* __restrict__ dst,
                                               int idx) {
    int m  = idx >> 5;
    int kb = idx & 31;
    const float* sp = src + (size_t)m * 512 + kb * 16;
    float e[16];
    #pragma unroll
    for (int q = 0; q < 4; q++) {
        float4 v = *reinterpret_cast<const float4*>(sp + q * 4);
        e[q * 4 + 0] = v.x; e[q * 4 + 1] = v.y;
        e[q * 4 + 2] = v.z; e[q * 4 + 3] = v.w;
    }
    uint4* dp = dst + (size_t)m * 128 + kb * 4;
    #pragma unroll
    for (int t = 0; t < 4; t++) {
        uint4 o;
        uint32_t loA, loB;
        split_pair(e[2 * t],     e[2 * t + 1], o.x, loA);
        split_pair(e[2 * t + 8], e[2 * t + 9], o.y, loB);
        o.z = loA; o.w = loB;
        dp[t] = o;
    }
}

__global__ void __launch_bounds__(256) pack_x(const float* __restrict__ src) {
    int idx = blockIdx.x * blockDim.x + threadIdx.x;
    if (idx < M1 * 32) pack_row_block(src, g_xfmt, idx);
}
__global__ void __launch_bounds__(256) pack_v(const float* __restrict__ src) {
    int idx = blockIdx.x * blockDim.x + threadIdx.x;
    if (idx < H * 32) pack_row_block(src, g_vfmt, idx);
}

// ===========================================================================
// Barrier primitives (no membar.gl -> no L1 flush)
// ===========================================================================
__device__ __forceinline__ void bar_arrive(unsigned int* p) {
    asm volatile("red.release.gpu.add.u32 [%0], 1;" :: "l"(p) : "memory");
}
__device__ __forceinline__ unsigned int bar_peek(const unsigned int* p) {
    unsigned int v;
    asm volatile("ld.acquire.gpu.u32 %0, [%1];" : "=r"(v) : "l"(p) : "memory");
    return v;
}

// ===========================================================================
// mma.sync m16n8k16 bf16 + cp.async helpers
// ===========================================================================
__device__ __forceinline__ void mma_bf16(float c[4],
                                         uint32_t a0, uint32_t a1,
                                         uint32_t a2, uint32_t a3,
                                         uint32_t b0, uint32_t b1) {
    asm volatile(
        "mma.sync.aligned.m16n8k16.row.col.f32.bf16.bf16.f32 "
        "{%0,%1,%2,%3}, {%4,%5,%6,%7}, {%8,%9}, {%0,%1,%2,%3};"
        : "+f"(c[0]), "+f"(c[1]), "+f"(c[2]), "+f"(c[3])
        : "r"(a0), "r"(a1), "r"(a2), "r"(a3), "r"(b0), "r"(b1));
}
__device__ __forceinline__ uint32_t smem_to_u32(const void* p) {
    uint32_t a;
    asm("{ .reg .u64 t; cvta.to.shared.u64 t, %1; cvt.u32.u64 %0, t; }"
        : "=r"(a) : "l"(p));
    return a;
}
__device__ __forceinline__ void cp16(uint32_t dst, const void* src) {
    asm volatile("cp.async.cg.shared.global [%0], [%1], 16;"
                 :: "r"(dst), "l"(src));
}
__device__ __forceinline__ void cp_commit() {
    asm volatile("cp.async.commit_group;");
}
template <int N>
__device__ __forceinline__ void cp_wait() {
    asm volatile("cp.async.wait_group %0;" :: "n"(N));
}

// ===========================================================================
// Phase 1: xV = x @ Vw^T + Vb via bf16x3 mma.sync.  (proven R9 code)
// ===========================================================================
__global__ void __launch_bounds__(256, 1) phase1_mma(
    const float* __restrict__ Vb, float* __restrict__ C)
{
    extern __shared__ char smem[];
    const uint32_t sbase = smem_to_u32(smem);

    const int tid  = threadIdx.x;
    const int wid  = tid >> 5;
    const int lane = tid & 31;
    const int bn   = blockIdx.x;           // 0..7
    const int bm   = blockIdx.y;           // 0..1023
    const int mi   = wid >> 1;             // 0..3
    const int ni   = wid & 1;              // 0..1
    const int m0   = mi * 32;
    const int n0   = ni * 32;
    const int g    = lane >> 2;
    const int t    = lane & 3;

    {
        const uint4* vsrc = g_vfmt + (size_t)(bn * 64) * 128;
        #pragma unroll
        for (int i = 0; i < 32; i++) {
            int j = tid + i * 256;
            int r = j >> 7;
            int u = j & 127;
            cp16(sbase + P1_SM_B + r * RSTR + u * 16, vsrc + (size_t)r * 128 + u);
        }
    }
    const uint4* xsrc = g_xfmt + (size_t)(bm * 128) * 128;
    #pragma unroll
    for (int i = 0; i < 8; i++) {
        int j = tid + i * 256;
        int r = j >> 4;
        int u = j & 15;
        cp16(sbase + P1_SM_A + r * RA + u * 16, xsrc + (size_t)r * 128 + u);
    }
    cp_commit();
    #pragma unroll
    for (int i = 0; i < 8; i++) {
        int j = tid + i * 256;
        int r = j >> 4;
        int u = j & 15;
        cp16(sbase + P1_SM_A + P1_ABUF + r * RA + u * 16,
             xsrc + (size_t)r * 128 + 16 + u);
    }
    cp_commit();

    float chh[2][4][4], chl[2][4][4], clh[2][4][4];
    #pragma unroll
    for (int a = 0; a < 2; a++)
        #pragma unroll
        for (int b = 0; b < 4; b++)
            #pragma unroll
            for (int c = 0; c < 4; c++) {
                chh[a][b][c] = 0.f; chl[a][b][c] = 0.f; clh[a][b][c] = 0.f;
            }

    const char* aBase = smem + P1_SM_A + (m0 + g) * RA + t * 16;
    const char* bBase = smem + P1_SM_B + (n0 + g) * RSTR + t * 16;

    #pragma unroll 1
    for (int c = 0; c < 8; ++c) {
        if (c < 7) cp_wait<1>(); else cp_wait<0>();
        __syncthreads();

        const char* aC = aBase + (c & 1) * P1_ABUF;
        #pragma unroll
        for (int kb2 = 0; kb2 < 4; kb2++) {
            uint4 A1 = *reinterpret_cast<const uint4*>(aC + kb2 * 64);
            uint4 A2 = *reinterpret_cast<const uint4*>(aC + 8 * RA + kb2 * 64);
            uint4 A3 = *reinterpret_cast<const uint4*>(aC + 16 * RA + kb2 * 64);
            uint4 A4 = *reinterpret_cast<const uint4*>(aC + 24 * RA + kb2 * 64);
            const char* bC = bBase + (c * 4 + kb2) * 64;
            uint4 Bv[4];
            Bv[0] = *reinterpret_cast<const uint4*>(bC);
            Bv[1] = *reinterpret_cast<const uint4*>(bC + 8 * RSTR);
            Bv[2] = *reinterpret_cast<const uint4*>(bC + 16 * RSTR);
            Bv[3] = *reinterpret_cast<const uint4*>(bC + 24 * RSTR);
            #pragma unroll
            for (int nj = 0; nj < 4; nj++) {
                mma_bf16(chh[0][nj], A1.x, A2.x, A1.y, A2.y, Bv[nj].x, Bv[nj].y);
                mma_bf16(chl[0][nj], A1.x, A2.x, A1.y, A2.y, Bv[nj].z, Bv[nj].w);
                mma_bf16(clh[0][nj], A1.z, A2.z, A1.w, A2.w, Bv[nj].x, Bv[nj].y);
                mma_bf16(chh[1][nj], A3.x, A4.x, A3.y, A4.y, Bv[nj].x, Bv[nj].y);
                mma_bf16(chl[1][nj], A3.x, A4.x, A3.y, A4.y, Bv[nj].z, Bv[nj].w);
                mma_bf16(clh[1][nj], A3.z, A4.z, A3.w, A4.w, Bv[nj].x, Bv[nj].y);
            }
        }
        __syncthreads();

        if (c + 2 < 8) {
            const int nb = (c + 2) & 1;
            #pragma unroll
            for (int i = 0; i < 8; i++) {
                int j = tid + i * 256;
                int r = j >> 4;
                int u = j & 15;
                cp16(sbase + P1_SM_A + nb * P1_ABUF + r * RA + u * 16,
                     xsrc + (size_t)r * 128 + (c + 2) * 16 + u);
            }
            cp_commit();
        }
    }

    #pragma unroll
    for (int mt = 0; mt < 2; mt++) {
        #pragma unroll
        for (int nj = 0; nj < 4; nj++) {
            const int col = bn * 64 + n0 + nj * 8 + 2 * t;
            const float2 bias = *reinterpret_cast<const float2*>(Vb + col);
            const int row0 = bm * 128 + m0 + mt * 16 + g;
            float s0 = chh[mt][nj][0] + chl[mt][nj][0] + clh[mt][nj][0] + bias.x;
            float s1 = chh[mt][nj][1] + chl[mt][nj][1] + clh[mt][nj][1] + bias.y;
            float s2 = chh[mt][nj][2] + chl[mt][nj][2] + clh[mt][nj][2] + bias.x;
            float s3 = chh[mt][nj][3] + chl[mt][nj][3] + clh[mt][nj][3] + bias.y;
            *reinterpret_cast<float2*>(C + (size_t)row0 * H + col) =
                make_float2(s0, s1);
            *reinterpret_cast<float2*>(C + (size_t)(row0 + 8) * H + col) =
                make_float2(s2, s3);
        }
    }
}

// ===========================================================================
// Phase 2: persistent mma.sync bf16x3 recurrence.
// R10 deltas vs proven R5: (1) A staging via cp.async in 2 halves overlapped
// with MMA; (2) g_hfmt stores + bar_arrive BEFORE h_seq stores; (3) fast
// truncation split in the epilogue.
// ===========================================================================
__global__ void __launch_bounds__(128, 1) rnn_steps_mma(
    const float* __restrict__ Wb,
    float* __restrict__ io)
{
    extern __shared__ char smem[];
    const uint32_t sbase = smem_to_u32(smem);

    const int tid  = threadIdx.x;
    const int wid  = tid >> 5;
    const int lane = tid & 31;
    const int bm   = blockIdx.x >> 4;          // 0..7
    const int bn   = blockIdx.x & 15;          // 0..15
    const int Rg0  = bm * 32;
    const int cg0  = bn * 32;

    const int mi = wid >> 1;
    const int ni = wid & 1;
    const int m0 = mi * 16;
    const int n0 = ni * 16;
    const int g  = lane >> 2;
    const int t  = lane & 3;

    // ---- Format resident W panel once (rows = out cols cg0..cg0+31) ----
    for (int l = 0; l < 32; l++) {
        int j  = tid + (l << 7);
        int r  = j >> 7;
        int k4 = (j & 127) * 4;
        uint4 v = *reinterpret_cast<const uint4*>(
            &g_whl[(size_t)(cg0 + r) * 512 + k4]);
        uint32_t hi0 = __byte_perm(v.x, v.y, 0x7632);
        uint32_t lo0 = __byte_perm(v.x, v.y, 0x5410);
        uint32_t hi1 = __byte_perm(v.z, v.w, 0x7632);
        uint32_t lo1 = __byte_perm(v.z, v.w, 0x5410);
        int kb   = k4 >> 4;
        int rem  = k4 & 15;
        int slot = (rem >= 8) ? 4 : 0;
        int t0   = (rem & 7) >> 1;
        char* base = smem + SM_W + r * RSTR + kb * 64 + t0 * 16 + slot;
        *reinterpret_cast<uint32_t*>(base)      = hi0;
        *reinterpret_cast<uint32_t*>(base + 8)  = lo0;
        *reinterpret_cast<uint32_t*>(base + 16) = hi1;
        *reinterpret_cast<uint32_t*>(base + 24) = lo1;
    }

    const char* aB = smem + SM_A + (m0 + g) * RSTR + t * 16;
    const char* bB = smem + SM_W + (n0 + g) * RSTR + t * 16;

    const int orow0 = Rg0 + m0 + g;
    const int c0    = cg0 + n0 + 2 * t;
    const float2 wbA = *reinterpret_cast<const float2*>(Wb + c0);
    const float2 wbB = *reinterpret_cast<const float2*>(Wb + c0 + 8);
    const int goff = ((cg0 + n0) >> 4) * 64 + t * 16;

    // ---- t = 0 : h_0 = tanh(xV_0 + Wb) ----
    {
        const int r  = tid >> 2;
        const int c8 = (tid & 3) * 8;
        const int gr = Rg0 + r;
        const float* xvp = io + (size_t)gr * H + cg0 + c8;
        float4 xv0 = __ldcg(reinterpret_cast<const float4*>(xvp));
        float4 xv1 = __ldcg(reinterpret_cast<const float4*>(xvp + 4));
        const float4 wb0 = *reinterpret_cast<const float4*>(Wb + cg0 + c8);
        const float4 wb1 = *reinterpret_cast<const float4*>(Wb + cg0 + c8 + 4);
        float h[8];
        h[0] = tanhf(xv0.x + wb0.x); h[1] = tanhf(xv0.y + wb0.y);
        h[2] = tanhf(xv0.z + wb0.z); h[3] = tanhf(xv0.w + wb0.w);
        h[4] = tanhf(xv1.x + wb1.x); h[5] = tanhf(xv1.y + wb1.y);
        h[6] = tanhf(xv1.z + wb1.z); h[7] = tanhf(xv1.w + wb1.w);
        char* gbase = reinterpret_cast<char*>(&g_hfmt[0][bm][0]) + r * RSTR;
        #pragma unroll
        for (int p = 0; p < 4; p++) {
            int k   = c8 + 2 * p;
            int km  = k & 15;
            int tg  = (km & 7) >> 1;
            int sl  = (km >= 8) ? 4 : 0;
            int kb  = (cg0 + k) >> 4;
            uint32_t hiw, low;
            split_pair_tr(h[2 * p], h[2 * p + 1], hiw, low);
            char* ptr = gbase + kb * 64 + tg * 16 + sl;
            __stcg(reinterpret_cast<uint32_t*>(ptr), hiw);
            __stcg(reinterpret_cast<uint32_t*>(ptr + 8), low);
        }
        __syncthreads();
        if (tid == 0) bar_arrive(&g_bar[bm]);
        float* op = io + (size_t)gr * H + cg0 + c8;
        *reinterpret_cast<float4*>(op)     = make_float4(h[0], h[1], h[2], h[3]);
        *reinterpret_cast<float4*>(op + 4) = make_float4(h[4], h[5], h[6], h[7]);
    }

    // ---- steps 1 .. S-1 ----
    for (int ts = 1; ts < S; ++ts) {
        // xV prefetch (independent of h_{t-1}; before the barrier)
        const float* iot = io + (size_t)ts * BH;
        float2 xva0 = __ldcg(reinterpret_cast<const float2*>(iot + (size_t)orow0 * H + c0));
        float2 xva1 = __ldcg(reinterpret_cast<const float2*>(iot + (size_t)orow0 * H + c0 + 8));
        float2 xvb0 = __ldcg(reinterpret_cast<const float2*>(iot + (size_t)(orow0 + 8) * H + c0));
        float2 xvb1 = __ldcg(reinterpret_cast<const float2*>(iot + (size_t)(orow0 + 8) * H + c0 + 8));

        // row-group barrier: all (bm,*) CTAs finished step ts-1
        if (tid == 0) {
            const unsigned target = (unsigned)ts * 16u;
            while (bar_peek(&g_bar[bm]) < target) { }
        }
        __syncthreads();

        // stage h_{t-1} panel via cp.async in two halves (32KB each)
        const uint4* src = &g_hfmt[(ts + 1) & 1][bm][0];
        #pragma unroll
        for (int i = 0; i < 16; i++) {
            int j = tid + (i << 7);            // 0..2047
            int r = j >> 6;                    // 0..31
            int u = j & 63;                    // kb 0..15
            cp16(sbase + SM_A + r * RSTR + u * 16, src + r * RU4 + u);
        }
        cp_commit();
        #pragma unroll
        for (int i = 0; i < 16; i++) {
            int j = tid + (i << 7);
            int r = j >> 6;
            int u = (j & 63) + 64;             // kb 16..31
            cp16(sbase + SM_A + r * RSTR + u * 16, src + r * RU4 + u);
        }
        cp_commit();

        float chh0[4] = {0.f,0.f,0.f,0.f}, chl0[4] = {0.f,0.f,0.f,0.f}, clh0[4] = {0.f,0.f,0.f,0.f};
        float chh1[4] = {0.f,0.f,0.f,0.f}, chl1[4] = {0.f,0.f,0.f,0.f}, clh1[4] = {0.f,0.f,0.f,0.f};

        // half 0 compute overlaps half 1 copy
        cp_wait<1>();
        __syncthreads();
        #pragma unroll 8
        for (int kb = 0; kb < 16; ++kb) {
            uint4 A1 = *reinterpret_cast<const uint4*>(aB + kb * 64);
            uint4 A2 = *reinterpret_cast<const uint4*>(aB + 8 * RSTR + kb * 64);
            uint4 B1 = *reinterpret_cast<const uint4*>(bB + kb * 64);
            uint4 B2 = *reinterpret_cast<const uint4*>(bB + 8 * RSTR + kb * 64);
            mma_bf16(chh0, A1.x, A2.x, A1.y, A2.y, B1.x, B1.y);
            mma_bf16(chh1, A1.x, A2.x, A1.y, A2.y, B2.x, B2.y);
            mma_bf16(chl0, A1.x, A2.x, A1.y, A2.y, B1.z, B1.w);
            mma_bf16(chl1, A1.x, A2.x, A1.y, A2.y, B2.z, B2.w);
            mma_bf16(clh0, A1.z, A2.z, A1.w, A2.w, B1.x, B1.y);
            mma_bf16(clh1, A1.z, A2.z, A1.w, A2.w, B2.x, B2.y);
        }
        cp_wait<0>();
        __syncthreads();
        #pragma unroll 8
        for (int kb = 16; kb < 32; ++kb) {
            uint4 A1 = *reinterpret_cast<const uint4*>(aB + kb * 64);
            uint4 A2 = *reinterpret_cast<const uint4*>(aB + 8 * RSTR + kb * 64);
            uint4 B1 = *reinterpret_cast<const uint4*>(bB + kb * 64);
            uint4 B2 = *reinterpret_cast<const uint4*>(bB + 8 * RSTR + kb * 64);
            mma_bf16(chh0, A1.x, A2.x, A1.y, A2.y, B1.x, B1.y);
            mma_bf16(chh1, A1.x, A2.x, A1.y, A2.y, B2.x, B2.y);
            mma_bf16(chl0, A1.x, A2.x, A1.y, A2.y, B1.z, B1.w);
            mma_bf16(chl1, A1.x, A2.x, A1.y, A2.y, B2.z, B2.w);
            mma_bf16(clh0, A1.z, A2.z, A1.w, A2.w, B1.x, B1.y);
            mma_bf16(clh1, A1.z, A2.z, A1.w, A2.w, B2.x, B2.y);
        }

        // epilogue: h = tanh(acc + xV + Wb)
        float h00 = tanhf(chh0[0] + chl0[0] + clh0[0] + xva0.x + wbA.x);
        float h01 = tanhf(chh0[1] + chl0[1] + clh0[1] + xva0.y + wbA.y);
        float h08 = tanhf(chh1[0] + chl1[0] + clh1[0] + xva1.x + wbB.x);
        float h09 = tanhf(chh1[1] + chl1[1] + clh1[1] + xva1.y + wbB.y);
        float h20 = tanhf(chh0[2] + chl0[2] + clh0[2] + xvb0.x + wbA.x);
        float h21 = tanhf(chh0[3] + chl0[3] + clh0[3] + xvb0.y + wbA.y);
        float h28 = tanhf(chh1[2] + chl1[2] + clh1[2] + xvb1.x + wbB.x);
        float h29 = tanhf(chh1[3] + chl1[3] + clh1[3] + xvb1.y + wbB.y);

        // critical-path stores FIRST: fragment-format h for next step
        {
            char* gb = reinterpret_cast<char*>(&g_hfmt[ts & 1][bm][0]);
            uint32_t hw0, lw0, hw1, lw1;
            split_pair_tr(h00, h01, hw0, lw0);
            split_pair_tr(h08, h09, hw1, lw1);
            __stcg(reinterpret_cast<uint4*>(gb + (m0 + g) * RSTR + goff),
                   make_uint4(hw0, hw1, lw0, lw1));
            split_pair_tr(h20, h21, hw0, lw0);
            split_pair_tr(h28, h29, hw1, lw1);
            __stcg(reinterpret_cast<uint4*>(gb + (m0 + g + 8) * RSTR + goff),
                   make_uint4(hw0, hw1, lw0, lw1));
        }
        __syncthreads();                       // g_hfmt stores + MMA reads done
        if (tid == 0) bar_arrive(&g_bar[bm]);  // release to consumers EARLY

        // h_seq outputs (off the inter-CTA critical path)
        float* op0 = io + (size_t)ts * BH + (size_t)orow0 * H + c0;
        float* op1 = io + (size_t)ts * BH + (size_t)(orow0 + 8) * H + c0;
        *reinterpret_cast<float2*>(op0)     = make_float2(h00, h01);
        *reinterpret_cast<float2*>(op0 + 8) = make_float2(h08, h09);
        *reinterpret_cast<float2*>(op1)     = make_float2(h20, h21);
        *reinterpret_cast<float2*>(op1 + 8) = make_float2(h28, h29);

        if (ts == S - 1) {
            float* lp0 = io + (size_t)S * BH + (size_t)orow0 * H + c0;
            float* lp1 = io + (size_t)S * BH + (size_t)(orow0 + 8) * H + c0;
            *reinterpret_cast<float2*>(lp0)     = make_float2(h00, h01);
            *reinterpret_cast<float2*>(lp0 + 8) = make_float2(h08, h09);
            *reinterpret_cast<float2*>(lp1)     = make_float2(h20, h21);
            *reinterpret_cast<float2*>(lp1 + 8) = make_float2(h28, h29);
        }
    }
}

// ===========================================================================
// kernel_launch
// Inputs: x (S,B,I), Vw (H,I), Vb (H), Ww (H,H), Wb (H)
// Output: h_seq (S,B,H) ++ h_last (B,H), fp32
// ===========================================================================
extern "C" void kernel_launch(void* const* d_in, const int* in_sizes, int n_in,
                              void* d_out, int out_size)
{
    const float* x  = (const float*)d_in[0];
    const float* Vw = (const float*)d_in[1];
    const float* Vb = (const float*)d_in[2];
    const float* Ww = (const float*)d_in[3];
    const float* Wb = (const float*)d_in[4];
    float* out = (float*)d_out;

    static bool attr_done = false;
    if (!attr_done) {
        cudaFuncSetAttribute(rnn_steps_mma,
                             cudaFuncAttributeMaxDynamicSharedMemorySize,
                             SMEM_P2);
        cudaFuncSetAttribute(phase1_mma,
                             cudaFuncAttributeMaxDynamicSharedMemorySize,
                             P1_SMEM);
        attr_done = true;
    }

    // barrier reset each launch -> deterministic across graph replays
    reset_ctr<<<1, 32>>>();

    convert_W<<<(H * H + 255) / 256, 256>>>(Ww);
    pack_x<<<(M1 * 32 + 255) / 256, 256>>>(x);
    pack_v<<<(H * 32 + 255) / 256, 256>>>(Vw);

    dim3 g1(8, 1024);
    phase1_mma<<<g1, 256, P1_SMEM>>>(Vb, out);

    rnn_steps_mma<<<128, 128, SMEM_P2>>>(Wb, out);
}